// round 15
// baseline (speedup 1.0000x reference)
#include <cuda_runtime.h>
#include <math.h>

// Problem constants
#define NCg    64
#define Cg     256
#define Dg     32
#define Kg     16
#define KBg    16
#define ALPHAg 16
#define Bg     16
#define HSg    128
#define HMg    128
#define HMODg  32
#define BSg    8
#define NTOT   (NCg*Cg)          // 16384
#define MODIN  113
#define MODINP 116
#define MODOUT 65
#define MODOUTP 68
#define QL     24                // quarter length: 4 x 24 = 96 rows (exact for msg MLP)
#define NXT    97                // xt rows actually used (state MLP reads row 96 as tail)
#define W1Q_SZ (4*6*2*64*4)      // 12288 floats
#define W2T_SZ (32*32*4)         // 4096 floats

// wtmod sub-offsets (mod weights staged in SMEM; dead after phase C; reused as l1 partials)
#define MODW1_OFF 0
#define MODW2_OFF (HMODg*MODINP)              // 3712
#define B2M_OFF   (MODW2_OFF + HMODg*MODOUTP) // 5888
#define WTMOD_SZ  (B2M_OFF + MODOUTP)         // 5956 floats (>= 16KB partials)

// Output layout: readout | h_new | msg | heb | heb_b
#define OFF_READOUT 0
#define OFF_HNEW   (BSg*NCg*Dg)
#define OFF_MSG    (OFF_HNEW + BSg*NTOT*Dg)
#define OFF_HEB    (OFF_MSG  + BSg*NTOT*Dg)
#define OFF_HEBB   (OFF_HEB  + BSg*NTOT*Kg)

typedef unsigned long long u64;

// Packed layer-1 weights, 4-way k-split (quarter length 24), plane-separated:
// idx = (((q*6+gl)*2 + p)*64 + s)*4 + r  ->  w1[2s+p][q*24 + gl*4 + r]
__device__ __align__(16) float g_w1q_s[W1Q_SZ];
__device__ __align__(16) float g_w1q_m[W1Q_SZ];
// State l1 tail column: g_wtail_s[h] = state_w1[h][96]
__device__ __align__(16) float g_wtail_s[HSg];
// Transposed layer-2 weights: g_w2t[(j*32 + d)*4 + r] = w2[d][4j + r]
__device__ __align__(16) float g_w2t_s[W2T_SZ];
__device__ __align__(16) float g_w2t_m[W2T_SZ];

__device__ __forceinline__ u64 fma2_(u64 a, u64 b, u64 c) {
    u64 d; asm("fma.rn.f32x2 %0, %1, %2, %3;" : "=l"(d) : "l"(a), "l"(b), "l"(c));
    return d;
}
__device__ __forceinline__ u64 add2_(u64 a, u64 b) {
    u64 d; asm("add.rn.f32x2 %0, %1, %2;" : "=l"(d) : "l"(a), "l"(b));
    return d;
}
__device__ __forceinline__ u64 pack2_(float lo, float hi) {
    u64 r; asm("mov.b64 %0, {%1, %2};" : "=l"(r) : "f"(lo), "f"(hi));
    return r;
}
__device__ __forceinline__ float2 unpack2_(u64 v) {
    float2 r; asm("mov.b64 {%0, %1}, %2;" : "=f"(r.x), "=f"(r.y) : "l"(v));
    return r;
}
// fast tanh: 1 - 2/(e^{2x}+1); saturates correctly at +-inf
__device__ __forceinline__ float ftanh(float x) {
    float t = __expf(2.f * x);
    return 1.f - __fdividef(2.f, t + 1.f);
}
__device__ __forceinline__ float sigmoidf_(float x) {
    return __fdividef(1.f, 1.f + __expf(-x));
}

// Multi-value butterfly: lane kd enters with v[k] = msg[kd]*neigh[k][kd], k=0..15.
// 5 rounds (16 SHFLs total). On exit, even lanes hold dot[k] for k = (kd>>1)&15.
__device__ __forceinline__ float multi_dot16(float* v, int kd, int& k_out)
{
    const bool h16 = (kd & 16) != 0;
    #pragma unroll
    for (int j = 0; j < 8; ++j) {
        float snd = h16 ? v[j] : v[j + 8];
        float r = __shfl_xor_sync(0xffffffffu, snd, 16);
        v[j] = h16 ? (v[j + 8] + r) : (v[j] + r);
    }
    const bool h8 = (kd & 8) != 0;
    #pragma unroll
    for (int j = 0; j < 4; ++j) {
        float snd = h8 ? v[j] : v[j + 4];
        float r = __shfl_xor_sync(0xffffffffu, snd, 8);
        v[j] = h8 ? (v[j + 4] + r) : (v[j] + r);
    }
    const bool h4 = (kd & 4) != 0;
    #pragma unroll
    for (int j = 0; j < 2; ++j) {
        float snd = h4 ? v[j] : v[j + 2];
        float r = __shfl_xor_sync(0xffffffffu, snd, 4);
        v[j] = h4 ? (v[j + 2] + r) : (v[j] + r);
    }
    const bool h2 = (kd & 2) != 0;
    {
        float snd = h2 ? v[0] : v[1];
        float r = __shfl_xor_sync(0xffffffffu, snd, 2);
        v[0] = h2 ? (v[1] + r) : (v[0] + r);
    }
    v[0] += __shfl_xor_sync(0xffffffffu, v[0], 1);
    k_out = (kd >> 1) & 15;
    return v[0];
}

#define PH 132   // hbuf pitch (132 mod 32 == 4 -> conflict-free float4 rows)

struct __align__(16) Smem {
    float wtmod[WTMOD_SZ];       // 5956 f : mod weights; then l1 partials
    float hbuf[BSg][PH];         // 1056 f : layer-1 output (tanh)
    float in[BSg][MODINP];       // 928 f  : mod_input rows, zero-padded
    float xt[NXT*8];             // 776 f  : xt[i*8+b], rows 0..96 (all written by EF)
    float outb[BSg][MODOUTP];    // 544 f
    float hid[HMODg][BSg];       // 256 f
    float msgv[BSg][33];         // 264 f
    float wsig[BSg][Kg];
    float wsigb[BSg][KBg];
    int   conn[Kg];
    int   bconn[KBg];
};  // ~39.4 KB -> 4 blocks/SM

// Layer-1: hbuf[b][h] = tanh( sum_i w1[h][i]*xt[i][b] + bias[h] )
// Thread t: q = t>>6 (k-quarter of 24 rows), s = t&63 -> h0 = 2s, h1 = 2s+1.
// Reduce map == compute map with bp = q: each thread KEEPS its own-quarter partial
// in registers; only 3 of 4 bp-groups are stored / 3 of 4 quarters loaded.
__device__ __forceinline__ void mlp_l1(Smem& s, int tid, const float* __restrict__ w1q,
                                       const float* __restrict__ wtail,
                                       const float* __restrict__ bias)
{
    const int q = tid >> 6, ss = tid & 63;
    u64 acc[8];
    #pragma unroll
    for (int j = 0; j < 8; ++j) acc[j] = 0ull;
    #pragma unroll
    for (int gl = 0; gl < 6; ++gl) {
        const float* gb = w1q + ((q*6 + gl)*2)*256;
        float4 wa = *(const float4*)(gb + ss*4);          // w[h0][i..i+3]
        float4 wb = *(const float4*)(gb + 256 + ss*4);    // w[h1][i..i+3]
        const float* xr = s.xt + (q*QL + gl*4)*8;
        #pragma unroll
        for (int r = 0; r < 4; ++r) {
            ulonglong2 xlo = *(const ulonglong2*)(xr + r*8);      // {b0,b1},{b2,b3}
            ulonglong2 xhi = *(const ulonglong2*)(xr + r*8 + 4);  // {b4,b5},{b6,b7}
            float war = (r == 0) ? wa.x : (r == 1) ? wa.y : (r == 2) ? wa.z : wa.w;
            float wbr = (r == 0) ? wb.x : (r == 1) ? wb.y : (r == 2) ? wb.z : wb.w;
            u64 w0 = pack2_(war, war);
            u64 w1p = pack2_(wbr, wbr);
            acc[0] = fma2_(w0,  xlo.x, acc[0]); acc[1] = fma2_(w0,  xlo.y, acc[1]);
            acc[2] = fma2_(w0,  xhi.x, acc[2]); acc[3] = fma2_(w0,  xhi.y, acc[3]);
            acc[4] = fma2_(w1p, xlo.x, acc[4]); acc[5] = fma2_(w1p, xlo.y, acc[5]);
            acc[6] = fma2_(w1p, xhi.x, acc[6]); acc[7] = fma2_(w1p, xhi.y, acc[7]);
        }
    }
    // state-MLP tail: i = 96 (decay row), added by quarter-0 threads only
    if (wtail != nullptr && q == 0) {
        float2 wt = *(const float2*)(wtail + 2*ss);       // {w[h0][96], w[h1][96]}
        const float* xr = s.xt + 96*8;
        ulonglong2 xlo = *(const ulonglong2*)(xr);
        ulonglong2 xhi = *(const ulonglong2*)(xr + 4);
        u64 w0 = pack2_(wt.x, wt.x);
        u64 w1p = pack2_(wt.y, wt.y);
        acc[0] = fma2_(w0,  xlo.x, acc[0]); acc[1] = fma2_(w0,  xlo.y, acc[1]);
        acc[2] = fma2_(w0,  xhi.x, acc[2]); acc[3] = fma2_(w0,  xhi.y, acc[3]);
        acc[4] = fma2_(w1p, xlo.x, acc[4]); acc[5] = fma2_(w1p, xlo.y, acc[5]);
        acc[6] = fma2_(w1p, xhi.x, acc[6]); acc[7] = fma2_(w1p, xhi.y, acc[7]);
    }
    // store only the 3 bp-groups NOT owned by this thread's reduce role (bp != q)
    u64* part = (u64*)s.wtmod;
    u64* pq = part + q*(4*128);
    #pragma unroll
    for (int bp = 0; bp < 4; ++bp) {
        if (bp != q) {
            ulonglong2 v; v.x = acc[bp]; v.y = acc[4 + bp];
            *(ulonglong2*)(pq + bp*128 + 2*ss) = v;
        }
    }
    __syncthreads();
    // reduce: this thread owns (b pair = q, h pair = 2ss); own quarter from registers
    u64 s0 = acc[q], s1 = acc[4 + q];
    #pragma unroll
    for (int qq = 0; qq < 4; ++qq) {
        if (qq != q) {
            ulonglong2 p = *(const ulonglong2*)(part + (qq*4 + q)*128 + 2*ss);
            s0 = add2_(s0, p.x);
            s1 = add2_(s1, p.y);
        }
    }
    float2 bb = *(const float2*)(bias + 2*ss);
    float2 v0 = unpack2_(s0), v1 = unpack2_(s1);   // v0: h=2ss {b even,odd}; v1: h=2ss+1
    const int b0 = 2*q, b1 = 2*q + 1;
    *(float2*)(&s.hbuf[b0][2*ss]) = make_float2(ftanh(v0.x + bb.x), ftanh(v1.x + bb.y));
    *(float2*)(&s.hbuf[b1][2*ss]) = make_float2(ftanh(v0.y + bb.x), ftanh(v1.y + bb.y));
}

// Layer-2: acc[b][d] = bias2[d] + sum_h hbuf[b][h] * w2[d][h]
__device__ __forceinline__ float mlp_l2(const Smem& s, int tid,
                                        const float* __restrict__ w2t,
                                        const float* __restrict__ bias2,
                                        int& b_, int& d_)
{
    const int w = tid >> 5, lane = tid & 31;
    const int b = lane & 7, d = w*4 + (lane >> 3);
    const ulonglong2* hv = (const ulonglong2*)(&s.hbuf[b][0]);
    u64 a0 = 0ull, a1 = 0ull, a2 = 0ull, a3 = 0ull;
    #pragma unroll
    for (int j = 0; j < HSg/4; j += 2) {
        ulonglong2 w0 = *(const ulonglong2*)(w2t + (j*32 + d)*4);
        ulonglong2 w1 = *(const ulonglong2*)(w2t + ((j+1)*32 + d)*4);
        ulonglong2 h0 = hv[j], h1 = hv[j+1];
        a0 = fma2_(w0.x, h0.x, a0); a1 = fma2_(w0.y, h0.y, a1);
        a2 = fma2_(w1.x, h1.x, a2); a3 = fma2_(w1.y, h1.y, a3);
    }
    float2 r0 = unpack2_(a0), r1 = unpack2_(a1), r2 = unpack2_(a2), r3 = unpack2_(a3);
    b_ = b; d_ = d;
    return bias2[d] + ((r0.x + r0.y) + (r1.x + r1.y)) + ((r2.x + r2.y) + (r3.x + r3.y));
}

__global__ void __launch_bounds__(256, 4)
cell_kernel(const float* __restrict__ x,
            const float* __restrict__ h_in,
            const float* __restrict__ prevmsg,
            const float* __restrict__ decay_logit,
            const float* __restrict__ prim,
            const float* __restrict__ heb_tr,
            const float* __restrict__ heb_trb,
            const float* __restrict__ state_b1, const float* __restrict__ state_b2,
            const float* __restrict__ msg_b1,  const float* __restrict__ msg_b2,
            const float* __restrict__ mod_w1,  const float* __restrict__ mod_b1,
            const float* __restrict__ mod_w2,  const float* __restrict__ mod_b2,
            const float* __restrict__ neuron_id,
            const int*   __restrict__ conn_idx,
            const int*   __restrict__ bconn_idx,
            float* __restrict__ dout)
{
    extern __shared__ char smraw[];
    Smem& s = *reinterpret_cast<Smem*>(smraw);
    const int tid = threadIdx.x;
    const int n  = blockIdx.x;
    const int nc = n >> 8;
    const int c  = n & 255;
    const bool bord = (c >= ALPHAg) && (c < ALPHAg + Bg);

    // ---------------- Phase A: stage mod_input + mod weights --------------------------
    {
        float v1[15];
        #pragma unroll
        for (int j = 0; j < 15; ++j) {
            int idx = tid + 256*j;
            v1[j] = (idx < HMODg*MODIN) ? __ldg(mod_w1 + n*(HMODg*MODIN) + idx) : 0.f;
        }
        float v2[9];
        #pragma unroll
        for (int j = 0; j < 9; ++j) {
            int idx = tid + 256*j;
            v2[j] = (idx < HMODg*MODOUT) ? __ldg(mod_w2 + n*(HMODg*MODOUT) + idx) : 0.f;
        }
        #pragma unroll
        for (int j = 0; j < 15; ++j) {
            int idx = tid + 256*j;
            if (idx < HMODg*MODIN) {
                int o = idx / MODIN, i = idx - o*MODIN;
                s.wtmod[MODW1_OFF + o*MODINP + i] = v1[j];
            }
        }
        #pragma unroll
        for (int j = 0; j < 9; ++j) {
            int idx = tid + 256*j;
            if (idx < HMODg*MODOUT) {
                int o = idx / MODOUT, i = idx - o*MODOUT;
                s.wtmod[MODW2_OFF + o*MODOUTP + i] = v2[j];
            }
        }
    }
    {   // s.in: b = tid>>5, i = lane + 32j
        const int b = tid >> 5, lane = tid & 31;
        const int base = ((b*NCg + nc)*Cg + c);
        #pragma unroll
        for (int j = 0; j < 4; ++j) {
            int i = lane + 32*j;
            if (i < MODINP) {
                float v = 0.f;
                if (i < Kg)       v = heb_tr[base*Kg + i];
                else if (i < 48)  { int d = i - 16; v = h_in[base*Dg + d];
                                    if (c < ALPHAg) v += x[b*(NCg*Dg) + nc*Dg + d]; }
                else if (i == 48) v = decay_logit[base];
                else if (i < 81)  v = prim[base*Dg + (i-49)];
                else if (i < MODIN) v = neuron_id[(nc*Cg+c)*Dg + (i-81)];
                s.in[b][i] = v;
            }
        }
    }
    // zero the pad columns (avoid NaN x 0)
    if (tid < 96) {
        int o = tid / 3, r = tid - 3*(tid/3);
        s.wtmod[MODW1_OFF + o*MODINP + MODIN + r] = 0.f;
        s.wtmod[MODW2_OFF + o*MODOUTP + MODOUT + r] = 0.f;
    }
    if (tid >= 96 && tid < 96 + MODOUTP) {
        int j = tid - 96;
        s.wtmod[B2M_OFF + j] = (j < MODOUT) ? mod_b2[n*MODOUT + j] : 0.f;
    }
    if (tid >= 160 && tid < 160+Kg) s.conn[tid-160] = conn_idx[(nc*Cg+c)*Kg + (tid-160)];
    if (bord && tid >= 176 && tid < 176+KBg)
        s.bconn[tid-176] = bconn_idx[(nc*Bg + (c-ALPHAg))*KBg + (tid-176)];
    __syncthreads();  // S1

    // ---------------- Phase B: mod hidden = tanh(modw1 @ in + b1)  (FFMA2) --------------
    {
        int o = tid >> 3, b = tid & 7;
        const ulonglong2* wv = (const ulonglong2*)(s.wtmod + MODW1_OFF + o*MODINP);
        const ulonglong2* xv = (const ulonglong2*)(&s.in[b][0]);
        u64 a0 = 0ull, a1 = 0ull;
        #pragma unroll
        for (int j = 0; j < MODINP/4; ++j) {
            ulonglong2 w = wv[j], xx = xv[j];
            a0 = fma2_(w.x, xx.x, a0);
            a1 = fma2_(w.y, xx.y, a1);
        }
        float2 p0 = unpack2_(a0), p1 = unpack2_(a1);
        s.hid[o][b] = ftanh(mod_b1[n*HMODg + o] + (p0.x + p0.y) + (p1.x + p1.y));
    }
    __syncthreads();  // S2

    // ---------------- Phase C: outb = hid @ modw2 + b2  (FFMA2) --------------------------
    if (tid < 136) {
        int b = tid / 17, og = tid % 17;
        const float* mw2 = s.wtmod + MODW2_OFF;
        u64 a0 = 0ull, a1 = 0ull;
        #pragma unroll
        for (int hh = 0; hh < HMODg; ++hh) {
            float hvv = s.hid[hh][b];
            u64 hp = pack2_(hvv, hvv);
            ulonglong2 wq = *(const ulonglong2*)(mw2 + hh*MODOUTP + og*4);
            a0 = fma2_(hp, wq.x, a0);
            a1 = fma2_(hp, wq.y, a1);
        }
        float2 q0 = unpack2_(a0), q1 = unpack2_(a1);
        float4 bz = *(const float4*)(s.wtmod + B2M_OFF + og*4);
        float4 r = make_float4(q0.x + bz.x, q0.y + bz.y, q1.x + bz.z, q1.y + bz.w);
        *(float4*)(&s.outb[b][og*4]) = r;
    }
    __syncthreads();  // S3  (wtmod now dead -> reused as l1 partials)

    // ---------------- Phase EF: w_sig + xt fill + agg gathers ----------------------------
    {
        const int wb = tid >> 5, lane = tid & 31;     // warp wb owns batch row wb
        {
            int i = tid >> 3, b = tid & 7;
            s.xt[i*8 + b] = s.in[b][16 + i];          // rows 0..31 = h
        }
        for (int idx = tid; idx < 264; idx += 256) {  // rows 64..95 prim, 96 decay
            int i = idx >> 3, b = idx & 7;
            float v = (i < 32) ? s.outb[b][33 + i] : s.outb[b][32];
            s.xt[(64 + i)*8 + b] = v;
        }
        if (lane < 16) {
            s.wsig[wb][lane] = sigmoidf_(s.outb[wb][lane] + s.in[wb][lane]);
        } else if (bord) {
            int k = lane - 16;
            s.wsigb[wb][k] = sigmoidf_(s.outb[wb][16 + k]
                          + heb_trb[((wb*NCg + nc)*Bg + (c - ALPHAg))*KBg + k]);
        }
        __syncwarp();
        float acc = 0.f;
        #pragma unroll
        for (int k = 0; k < Kg; ++k)
            acc = fmaf(s.wsig[wb][k],
                       prevmsg[((wb*NCg + nc)*Cg + s.conn[k])*Dg + lane], acc);
        if (bord) {
            #pragma unroll
            for (int k = 0; k < KBg; ++k) {
                int j = s.bconn[k];
                acc = fmaf(s.wsigb[wb][k],
                           prevmsg[((wb*NCg + (j >> 4))*Cg + ALPHAg + (j & 15))*Dg + lane], acc);
            }
        }
        s.xt[(32 + lane)*8 + wb] = acc;               // rows 32..63 = agg
    }
    __syncthreads();  // S4

    // ---------------- Phase G: shid -> hbuf (k-split l1 + tail; internal sync) -----------
    mlp_l1(s, tid, g_w1q_s, g_wtail_s, state_b1);
    __syncthreads();  // S5

    // ---------------- Phase H: delta, h_new + nid-to-xt -----------------------------------
    {
        int b, d;
        float acc = mlp_l2(s, tid, g_w2t_s, state_b2, b, d);
        float dec = sigmoidf_(s.outb[b][32]);
        float hv  = s.xt[d*8 + b];
        float hn  = dec*hv + (1.f - dec)*ftanh(acc);
        s.xt[d*8 + b] = hn;
        dout[OFF_HNEW + (((b*NCg + nc)*Cg + c)*Dg + d)] = hn;
    }
    {   // xt rows 64..95 = nid (replaces prim); row 96 unused by msg MLP (NI=96)
        int i = tid >> 3, b = tid & 7;
        s.xt[(64 + i)*8 + b] = s.in[b][81 + i];
    }
    __syncthreads();  // S6

    // ---------------- Phase I: mhid -> hbuf (NI=96 exact, no tail) -----------------------
    mlp_l1(s, tid, g_w1q_m, nullptr, msg_b1);
    __syncthreads();  // S7

    // ---------------- Phase J: msg + readout atomics ---------------------------------------
    {
        int b, d;
        float acc = mlp_l2(s, tid, g_w2t_m, msg_b2, b, d);
        s.msgv[b][d] = acc;
        dout[OFF_MSG + (((b*NCg + nc)*Cg + c)*Dg + d)] = acc;
        if (c >= Cg - ALPHAg)
            atomicAdd(&dout[OFF_READOUT + (b*NCg + nc)*Dg + d], acc * (1.f/ALPHAg));
    }
    __syncthreads();  // S8

    // ---------------- Phase K: Hebbian (multi-value butterfly) -----------------------------
    {
        const int kb = tid >> 5, kd = tid & 31;
        float msgval = s.msgv[kb][kd];
        {
            float v[16];
            #pragma unroll
            for (int k = 0; k < Kg; ++k)
                v[k] = msgval * prevmsg[((kb*NCg + nc)*Cg + s.conn[k])*Dg + kd];
            int k;
            float dot = multi_dot16(v, kd, k);
            if ((kd & 1) == 0) {
                float out = 0.9f * s.in[kb][k] + 0.003125f * dot;
                dout[OFF_HEB + (((kb*NCg + nc)*Cg + c)*Kg + k)] = out;
            }
        }
        if (bord) {
            float v[16];
            #pragma unroll
            for (int k = 0; k < KBg; ++k) {
                int j = s.bconn[k];
                v[k] = msgval * prevmsg[((kb*NCg + (j >> 4))*Cg + ALPHAg + (j & 15))*Dg + kd];
            }
            int k;
            float dot = multi_dot16(v, kd, k);
            if ((kd & 1) == 0) {
                float out = 0.9f * heb_trb[((kb*NCg + nc)*Bg + (c - ALPHAg))*KBg + k]
                          + 0.003125f * dot;
                dout[OFF_HEBB + (((kb*NCg + nc)*Bg + (c - ALPHAg))*KBg + k)] = out;
            }
        }
    }
}

// prep: zero readout + pack layer-1 weights (QL=24 quarters + state tail) + transpose w2
__global__ void prep_kernel(const float* __restrict__ sw1, const float* __restrict__ mw1,
                            const float* __restrict__ sw2, const float* __restrict__ mw2,
                            float* __restrict__ dout)
{
    int idx = blockIdx.x * 256 + threadIdx.x;
    if (idx < BSg*NCg*Dg) dout[OFF_READOUT + idx] = 0.f;
    if (idx < W1Q_SZ) {
        int r = idx & 3, t = idx >> 2;
        int ss = t & 63; t >>= 6;
        int p = t & 1; t >>= 1;
        int gl = t % 6, q = t / 6;
        int i = q*QL + gl*4 + r;          // 0..95 always
        int h = 2*ss + p;
        g_w1q_s[idx] = sw1[h*97 + i];
        g_w1q_m[idx] = mw1[h*96 + i];
    }
    if (idx < HSg) g_wtail_s[idx] = sw1[idx*97 + 96];
    if (idx < W2T_SZ) {
        int r = idx & 3, d = (idx >> 2) & 31, j = idx >> 7;
        g_w2t_s[idx] = sw2[d*HSg + 4*j + r];
        g_w2t_m[idx] = mw2[d*HMg + 4*j + r];
    }
}

extern "C" void kernel_launch(void* const* d_in, const int* in_sizes, int n_in,
                              void* d_out, int out_size)
{
    (void)in_sizes; (void)n_in; (void)out_size;
    const float* x           = (const float*)d_in[0];
    const float* h_in        = (const float*)d_in[1];
    const float* prevmsg     = (const float*)d_in[2];
    const float* decay_logit = (const float*)d_in[3];
    const float* prim        = (const float*)d_in[4];
    const float* heb_tr      = (const float*)d_in[5];
    const float* heb_trb     = (const float*)d_in[6];
    const float* state_w1    = (const float*)d_in[7];
    const float* state_b1    = (const float*)d_in[8];
    const float* state_w2    = (const float*)d_in[9];
    const float* state_b2    = (const float*)d_in[10];
    const float* msg_w1      = (const float*)d_in[11];
    const float* msg_b1      = (const float*)d_in[12];
    const float* msg_w2      = (const float*)d_in[13];
    const float* msg_b2      = (const float*)d_in[14];
    const float* mod_w1      = (const float*)d_in[15];
    const float* mod_b1      = (const float*)d_in[16];
    const float* mod_w2      = (const float*)d_in[17];
    const float* mod_b2      = (const float*)d_in[18];
    const float* neuron_id   = (const float*)d_in[19];
    const int*   conn_idx    = (const int*)d_in[20];
    const int*   bconn_idx   = (const int*)d_in[21];
    float* dout = (float*)d_out;

    cudaFuncSetAttribute(cell_kernel,
                         cudaFuncAttributeMaxDynamicSharedMemorySize,
                         (int)sizeof(Smem));

    prep_kernel<<<(BSg*NCg*Dg + 255)/256, 256>>>(state_w1, msg_w1, state_w2, msg_w2, dout);
    cell_kernel<<<NTOT, 256, sizeof(Smem)>>>(
        x, h_in, prevmsg, decay_logit, prim, heb_tr, heb_trb,
        state_b1, state_b2, msg_b1, msg_b2,
        mod_w1, mod_b1, mod_w2, mod_b2,
        neuron_id, conn_idx, bconn_idx, dout);
}

// round 16
// speedup vs baseline: 1.1006x; 1.1006x over previous
#include <cuda_runtime.h>
#include <math.h>

// Problem constants
#define NCg    64
#define Cg     256
#define Dg     32
#define Kg     16
#define KBg    16
#define ALPHAg 16
#define Bg     16
#define HSg    128
#define HMg    128
#define HMODg  32
#define BSg    8
#define NTOT   (NCg*Cg)          // 16384
#define MODIN  113
#define MODINP 116
#define MODOUT 65
#define MODOUTP 68
#define QL     24                // quarter length: 4 x 24 = 96 rows (exact for msg MLP)
#define NXT    97                // xt rows actually used (state MLP reads row 96 as tail)
#define W1Q_SZ (4*6*2*64*4)      // 12288 floats
#define W2T_SZ (32*32*4)         // 4096 floats

// wtmod sub-offsets (mod weights staged in SMEM; dead after phase C; reused as l1 partials)
#define MODW1_OFF 0
#define MODW2_OFF (HMODg*MODINP)              // 3712
#define B2M_OFF   (MODW2_OFF + HMODg*MODOUTP) // 5888
#define WTMOD_SZ  (B2M_OFF + MODOUTP)         // 5956 floats (>= 16KB partials)

// Output layout: readout | h_new | msg | heb | heb_b
#define OFF_READOUT 0
#define OFF_HNEW   (BSg*NCg*Dg)
#define OFF_MSG    (OFF_HNEW + BSg*NTOT*Dg)
#define OFF_HEB    (OFF_MSG  + BSg*NTOT*Dg)
#define OFF_HEBB   (OFF_HEB  + BSg*NTOT*Kg)

typedef unsigned long long u64;

// Packed layer-1 weights, 4-way k-split (quarter length 24), plane-separated:
// idx = (((q*6+gl)*2 + p)*64 + s)*4 + r  ->  w1[2s+p][q*24 + gl*4 + r]
__device__ __align__(16) float g_w1q_s[W1Q_SZ];
__device__ __align__(16) float g_w1q_m[W1Q_SZ];
// State l1 tail column: g_wtail_s[h] = state_w1[h][96]
__device__ __align__(16) float g_wtail_s[HSg];
// Transposed layer-2 weights: g_w2t[(j*32 + d)*4 + r] = w2[d][4j + r]
__device__ __align__(16) float g_w2t_s[W2T_SZ];
__device__ __align__(16) float g_w2t_m[W2T_SZ];

__device__ __forceinline__ u64 fma2_(u64 a, u64 b, u64 c) {
    u64 d; asm("fma.rn.f32x2 %0, %1, %2, %3;" : "=l"(d) : "l"(a), "l"(b), "l"(c));
    return d;
}
__device__ __forceinline__ u64 add2_(u64 a, u64 b) {
    u64 d; asm("add.rn.f32x2 %0, %1, %2;" : "=l"(d) : "l"(a), "l"(b));
    return d;
}
__device__ __forceinline__ u64 pack2_(float lo, float hi) {
    u64 r; asm("mov.b64 %0, {%1, %2};" : "=l"(r) : "f"(lo), "f"(hi));
    return r;
}
__device__ __forceinline__ float2 unpack2_(u64 v) {
    float2 r; asm("mov.b64 {%0, %1}, %2;" : "=f"(r.x), "=f"(r.y) : "l"(v));
    return r;
}
// fast tanh: 1 - 2/(e^{2x}+1); saturates correctly at +-inf
__device__ __forceinline__ float ftanh(float x) {
    float t = __expf(2.f * x);
    return 1.f - __fdividef(2.f, t + 1.f);
}
__device__ __forceinline__ float sigmoidf_(float x) {
    return __fdividef(1.f, 1.f + __expf(-x));
}

// Multi-value butterfly: lane kd enters with v[k] = msg[kd]*neigh[k][kd], k=0..15.
// 5 rounds (16 SHFLs total). On exit, even lanes hold dot[k] for k = (kd>>1)&15.
__device__ __forceinline__ float multi_dot16(float* v, int kd, int& k_out)
{
    const bool h16 = (kd & 16) != 0;
    #pragma unroll
    for (int j = 0; j < 8; ++j) {
        float snd = h16 ? v[j] : v[j + 8];
        float r = __shfl_xor_sync(0xffffffffu, snd, 16);
        v[j] = h16 ? (v[j + 8] + r) : (v[j] + r);
    }
    const bool h8 = (kd & 8) != 0;
    #pragma unroll
    for (int j = 0; j < 4; ++j) {
        float snd = h8 ? v[j] : v[j + 4];
        float r = __shfl_xor_sync(0xffffffffu, snd, 8);
        v[j] = h8 ? (v[j + 4] + r) : (v[j] + r);
    }
    const bool h4 = (kd & 4) != 0;
    #pragma unroll
    for (int j = 0; j < 2; ++j) {
        float snd = h4 ? v[j] : v[j + 2];
        float r = __shfl_xor_sync(0xffffffffu, snd, 4);
        v[j] = h4 ? (v[j + 2] + r) : (v[j] + r);
    }
    const bool h2 = (kd & 2) != 0;
    {
        float snd = h2 ? v[0] : v[1];
        float r = __shfl_xor_sync(0xffffffffu, snd, 2);
        v[0] = h2 ? (v[1] + r) : (v[0] + r);
    }
    v[0] += __shfl_xor_sync(0xffffffffu, v[0], 1);
    k_out = (kd >> 1) & 15;
    return v[0];
}

#define PH 132   // hbuf pitch (132 mod 32 == 4 -> conflict-free float4 rows)

struct __align__(16) Smem {
    float wtmod[WTMOD_SZ];       // 5956 f : mod weights; then l1 partials
    float hbuf[BSg][PH];         // 1056 f : layer-1 output (tanh)
    float in[BSg][MODINP];       // 928 f  : mod_input rows, zero-padded
    float xt[NXT*8];             // 776 f  : xt[i*8+b], rows 0..96 (all written by EF)
    float outb[BSg][MODOUTP];    // 544 f
    float hid[HMODg][BSg];       // 256 f
    float msgv[BSg][33];         // 264 f
    float wsig[BSg][Kg];
    float wsigb[BSg][KBg];
    int   conn[Kg];
    int   bconn[KBg];
};  // ~39.4 KB -> 4 blocks/SM

// Layer-1: hbuf[b][h] = tanh( sum_i w1[h][i]*xt[i][b] + bias[h] )
// Thread t: q = t>>6 (k-quarter of 24 rows), s = t&63 -> h0 = 2s, h1 = 2s+1.
// Reduce role (bp,s2) == compute role (q,ss): own-quarter partial stays in registers
// (extracted via warp-uniform branch on q -- NO dynamic register indexing).
__device__ __forceinline__ void mlp_l1(Smem& s, int tid, const float* __restrict__ w1q,
                                       const float* __restrict__ wtail,
                                       const float* __restrict__ bias)
{
    const int q = tid >> 6, ss = tid & 63;
    u64 acc[8];
    #pragma unroll
    for (int j = 0; j < 8; ++j) acc[j] = 0ull;
    #pragma unroll
    for (int gl = 0; gl < 6; ++gl) {
        const float* gb = w1q + ((q*6 + gl)*2)*256;
        float4 wa = *(const float4*)(gb + ss*4);          // w[h0][i..i+3]
        float4 wb = *(const float4*)(gb + 256 + ss*4);    // w[h1][i..i+3]
        const float* xr = s.xt + (q*QL + gl*4)*8;
        #pragma unroll
        for (int r = 0; r < 4; ++r) {
            ulonglong2 xlo = *(const ulonglong2*)(xr + r*8);      // {b0,b1},{b2,b3}
            ulonglong2 xhi = *(const ulonglong2*)(xr + r*8 + 4);  // {b4,b5},{b6,b7}
            float war = (r == 0) ? wa.x : (r == 1) ? wa.y : (r == 2) ? wa.z : wa.w;
            float wbr = (r == 0) ? wb.x : (r == 1) ? wb.y : (r == 2) ? wb.z : wb.w;
            u64 w0 = pack2_(war, war);
            u64 w1p = pack2_(wbr, wbr);
            acc[0] = fma2_(w0,  xlo.x, acc[0]); acc[1] = fma2_(w0,  xlo.y, acc[1]);
            acc[2] = fma2_(w0,  xhi.x, acc[2]); acc[3] = fma2_(w0,  xhi.y, acc[3]);
            acc[4] = fma2_(w1p, xlo.x, acc[4]); acc[5] = fma2_(w1p, xlo.y, acc[5]);
            acc[6] = fma2_(w1p, xhi.x, acc[6]); acc[7] = fma2_(w1p, xhi.y, acc[7]);
        }
    }
    // state-MLP tail: i = 96 (decay row), added by quarter-0 threads only
    if (wtail != nullptr && q == 0) {
        float2 wt = *(const float2*)(wtail + 2*ss);       // {w[h0][96], w[h1][96]}
        const float* xr = s.xt + 96*8;
        ulonglong2 xlo = *(const ulonglong2*)(xr);
        ulonglong2 xhi = *(const ulonglong2*)(xr + 4);
        u64 w0 = pack2_(wt.x, wt.x);
        u64 w1p = pack2_(wt.y, wt.y);
        acc[0] = fma2_(w0,  xlo.x, acc[0]); acc[1] = fma2_(w0,  xlo.y, acc[1]);
        acc[2] = fma2_(w0,  xhi.x, acc[2]); acc[3] = fma2_(w0,  xhi.y, acc[3]);
        acc[4] = fma2_(w1p, xlo.x, acc[4]); acc[5] = fma2_(w1p, xlo.y, acc[5]);
        acc[6] = fma2_(w1p, xhi.x, acc[6]); acc[7] = fma2_(w1p, xhi.y, acc[7]);
    }
    // store partials ONLY for bp != q (static acc indices, warp-uniform predicates)
    u64* part = (u64*)s.wtmod;
    u64* pq = part + q*(4*128);
    #pragma unroll
    for (int bp = 0; bp < 4; ++bp) {
        if (bp != q) {
            ulonglong2 v; v.x = acc[bp]; v.y = acc[4 + bp];
            *(ulonglong2*)(pq + bp*128 + 2*ss) = v;
        }
    }
    __syncthreads();
    // own-quarter partial from registers via warp-uniform branch (q = tid>>6)
    u64 s0, s1;
    if (q == 0)      { s0 = acc[0]; s1 = acc[4]; }
    else if (q == 1) { s0 = acc[1]; s1 = acc[5]; }
    else if (q == 2) { s0 = acc[2]; s1 = acc[6]; }
    else             { s0 = acc[3]; s1 = acc[7]; }
    #pragma unroll
    for (int qq = 0; qq < 4; ++qq) {
        if (qq != q) {
            ulonglong2 p = *(const ulonglong2*)(part + (qq*4 + q)*128 + 2*ss);
            s0 = add2_(s0, p.x);
            s1 = add2_(s1, p.y);
        }
    }
    float2 bb = *(const float2*)(bias + 2*ss);
    float2 v0 = unpack2_(s0), v1 = unpack2_(s1);   // v0: h=2ss {b even,odd}; v1: h=2ss+1
    const int b0 = 2*q, b1 = 2*q + 1;
    s.hbuf[b0][2*ss]   = ftanh(v0.x + bb.x);
    s.hbuf[b1][2*ss]   = ftanh(v0.y + bb.x);
    s.hbuf[b0][2*ss+1] = ftanh(v1.x + bb.y);
    s.hbuf[b1][2*ss+1] = ftanh(v1.y + bb.y);
}

// Layer-2: acc[b][d] = bias2[d] + sum_h hbuf[b][h] * w2[d][h]
__device__ __forceinline__ float mlp_l2(const Smem& s, int tid,
                                        const float* __restrict__ w2t,
                                        const float* __restrict__ bias2,
                                        int& b_, int& d_)
{
    const int w = tid >> 5, lane = tid & 31;
    const int b = lane & 7, d = w*4 + (lane >> 3);
    const ulonglong2* hv = (const ulonglong2*)(&s.hbuf[b][0]);
    u64 a0 = 0ull, a1 = 0ull, a2 = 0ull, a3 = 0ull;
    #pragma unroll
    for (int j = 0; j < HSg/4; j += 2) {
        ulonglong2 w0 = *(const ulonglong2*)(w2t + (j*32 + d)*4);
        ulonglong2 w1 = *(const ulonglong2*)(w2t + ((j+1)*32 + d)*4);
        ulonglong2 h0 = hv[j], h1 = hv[j+1];
        a0 = fma2_(w0.x, h0.x, a0); a1 = fma2_(w0.y, h0.y, a1);
        a2 = fma2_(w1.x, h1.x, a2); a3 = fma2_(w1.y, h1.y, a3);
    }
    float2 r0 = unpack2_(a0), r1 = unpack2_(a1), r2 = unpack2_(a2), r3 = unpack2_(a3);
    b_ = b; d_ = d;
    return bias2[d] + ((r0.x + r0.y) + (r1.x + r1.y)) + ((r2.x + r2.y) + (r3.x + r3.y));
}

__global__ void __launch_bounds__(256, 4)
cell_kernel(const float* __restrict__ x,
            const float* __restrict__ h_in,
            const float* __restrict__ prevmsg,
            const float* __restrict__ decay_logit,
            const float* __restrict__ prim,
            const float* __restrict__ heb_tr,
            const float* __restrict__ heb_trb,
            const float* __restrict__ state_b1, const float* __restrict__ state_b2,
            const float* __restrict__ msg_b1,  const float* __restrict__ msg_b2,
            const float* __restrict__ mod_w1,  const float* __restrict__ mod_b1,
            const float* __restrict__ mod_w2,  const float* __restrict__ mod_b2,
            const float* __restrict__ neuron_id,
            const int*   __restrict__ conn_idx,
            const int*   __restrict__ bconn_idx,
            float* __restrict__ dout)
{
    extern __shared__ char smraw[];
    Smem& s = *reinterpret_cast<Smem*>(smraw);
    const int tid = threadIdx.x;
    const int n  = blockIdx.x;
    const int nc = n >> 8;
    const int c  = n & 255;
    const bool bord = (c >= ALPHAg) && (c < ALPHAg + Bg);

    // ---------------- Phase A: stage mod_input + mod weights --------------------------
    {
        float v1[15];
        #pragma unroll
        for (int j = 0; j < 15; ++j) {
            int idx = tid + 256*j;
            v1[j] = (idx < HMODg*MODIN) ? __ldg(mod_w1 + n*(HMODg*MODIN) + idx) : 0.f;
        }
        float v2[9];
        #pragma unroll
        for (int j = 0; j < 9; ++j) {
            int idx = tid + 256*j;
            v2[j] = (idx < HMODg*MODOUT) ? __ldg(mod_w2 + n*(HMODg*MODOUT) + idx) : 0.f;
        }
        #pragma unroll
        for (int j = 0; j < 15; ++j) {
            int idx = tid + 256*j;
            if (idx < HMODg*MODIN) {
                int o = idx / MODIN, i = idx - o*MODIN;
                s.wtmod[MODW1_OFF + o*MODINP + i] = v1[j];
            }
        }
        #pragma unroll
        for (int j = 0; j < 9; ++j) {
            int idx = tid + 256*j;
            if (idx < HMODg*MODOUT) {
                int o = idx / MODOUT, i = idx - o*MODOUT;
                s.wtmod[MODW2_OFF + o*MODOUTP + i] = v2[j];
            }
        }
    }
    {   // s.in: b = tid>>5, i = lane + 32j
        const int b = tid >> 5, lane = tid & 31;
        const int base = ((b*NCg + nc)*Cg + c);
        #pragma unroll
        for (int j = 0; j < 4; ++j) {
            int i = lane + 32*j;
            if (i < MODINP) {
                float v = 0.f;
                if (i < Kg)       v = heb_tr[base*Kg + i];
                else if (i < 48)  { int d = i - 16; v = h_in[base*Dg + d];
                                    if (c < ALPHAg) v += x[b*(NCg*Dg) + nc*Dg + d]; }
                else if (i == 48) v = decay_logit[base];
                else if (i < 81)  v = prim[base*Dg + (i-49)];
                else if (i < MODIN) v = neuron_id[(nc*Cg+c)*Dg + (i-81)];
                s.in[b][i] = v;
            }
        }
    }
    // zero the pad columns (avoid NaN x 0)
    if (tid < 96) {
        int o = tid / 3, r = tid - 3*(tid/3);
        s.wtmod[MODW1_OFF + o*MODINP + MODIN + r] = 0.f;
        s.wtmod[MODW2_OFF + o*MODOUTP + MODOUT + r] = 0.f;
    }
    if (tid >= 96 && tid < 96 + MODOUTP) {
        int j = tid - 96;
        s.wtmod[B2M_OFF + j] = (j < MODOUT) ? mod_b2[n*MODOUT + j] : 0.f;
    }
    if (tid >= 160 && tid < 160+Kg) s.conn[tid-160] = conn_idx[(nc*Cg+c)*Kg + (tid-160)];
    if (bord && tid >= 176 && tid < 176+KBg)
        s.bconn[tid-176] = bconn_idx[(nc*Bg + (c-ALPHAg))*KBg + (tid-176)];
    __syncthreads();  // S1

    // ---------------- Phase B: mod hidden = tanh(modw1 @ in + b1)  (FFMA2) --------------
    {
        int o = tid >> 3, b = tid & 7;
        const ulonglong2* wv = (const ulonglong2*)(s.wtmod + MODW1_OFF + o*MODINP);
        const ulonglong2* xv = (const ulonglong2*)(&s.in[b][0]);
        u64 a0 = 0ull, a1 = 0ull;
        #pragma unroll
        for (int j = 0; j < MODINP/4; ++j) {
            ulonglong2 w = wv[j], xx = xv[j];
            a0 = fma2_(w.x, xx.x, a0);
            a1 = fma2_(w.y, xx.y, a1);
        }
        float2 p0 = unpack2_(a0), p1 = unpack2_(a1);
        s.hid[o][b] = ftanh(mod_b1[n*HMODg + o] + (p0.x + p0.y) + (p1.x + p1.y));
    }
    __syncthreads();  // S2

    // ---------------- Phase C: outb = hid @ modw2 + b2  (FFMA2) --------------------------
    if (tid < 136) {
        int b = tid / 17, og = tid % 17;
        const float* mw2 = s.wtmod + MODW2_OFF;
        u64 a0 = 0ull, a1 = 0ull;
        #pragma unroll
        for (int hh = 0; hh < HMODg; ++hh) {
            float hvv = s.hid[hh][b];
            u64 hp = pack2_(hvv, hvv);
            ulonglong2 wq = *(const ulonglong2*)(mw2 + hh*MODOUTP + og*4);
            a0 = fma2_(hp, wq.x, a0);
            a1 = fma2_(hp, wq.y, a1);
        }
        float2 q0 = unpack2_(a0), q1 = unpack2_(a1);
        float4 bz = *(const float4*)(s.wtmod + B2M_OFF + og*4);
        float4 r = make_float4(q0.x + bz.x, q0.y + bz.y, q1.x + bz.z, q1.y + bz.w);
        *(float4*)(&s.outb[b][og*4]) = r;
    }
    __syncthreads();  // S3  (wtmod now dead -> reused as l1 partials)

    // ---------------- Phase EF: w_sig + xt fill + agg gathers ----------------------------
    {
        const int wb = tid >> 5, lane = tid & 31;     // warp wb owns batch row wb
        {
            int i = tid >> 3, b = tid & 7;
            s.xt[i*8 + b] = s.in[b][16 + i];          // rows 0..31 = h
        }
        for (int idx = tid; idx < 264; idx += 256) {  // rows 64..95 prim, 96 decay
            int i = idx >> 3, b = idx & 7;
            float v = (i < 32) ? s.outb[b][33 + i] : s.outb[b][32];
            s.xt[(64 + i)*8 + b] = v;
        }
        if (lane < 16) {
            s.wsig[wb][lane] = sigmoidf_(s.outb[wb][lane] + s.in[wb][lane]);
        } else if (bord) {
            int k = lane - 16;
            s.wsigb[wb][k] = sigmoidf_(s.outb[wb][16 + k]
                          + heb_trb[((wb*NCg + nc)*Bg + (c - ALPHAg))*KBg + k]);
        }
        __syncwarp();
        float acc = 0.f;
        #pragma unroll
        for (int k = 0; k < Kg; ++k)
            acc = fmaf(s.wsig[wb][k],
                       prevmsg[((wb*NCg + nc)*Cg + s.conn[k])*Dg + lane], acc);
        if (bord) {
            #pragma unroll
            for (int k = 0; k < KBg; ++k) {
                int j = s.bconn[k];
                acc = fmaf(s.wsigb[wb][k],
                           prevmsg[((wb*NCg + (j >> 4))*Cg + ALPHAg + (j & 15))*Dg + lane], acc);
            }
        }
        s.xt[(32 + lane)*8 + wb] = acc;               // rows 32..63 = agg
    }
    __syncthreads();  // S4

    // ---------------- Phase G: shid -> hbuf (k-split l1 + tail; internal sync) -----------
    mlp_l1(s, tid, g_w1q_s, g_wtail_s, state_b1);
    __syncthreads();  // S5

    // ---------------- Phase H: delta, h_new + nid-to-xt -----------------------------------
    {
        int b, d;
        float acc = mlp_l2(s, tid, g_w2t_s, state_b2, b, d);
        float dec = sigmoidf_(s.outb[b][32]);
        float hv  = s.xt[d*8 + b];
        float hn  = dec*hv + (1.f - dec)*ftanh(acc);
        s.xt[d*8 + b] = hn;
        dout[OFF_HNEW + (((b*NCg + nc)*Cg + c)*Dg + d)] = hn;
    }
    {   // xt rows 64..95 = nid (replaces prim); row 96 unused by msg MLP (NI=96)
        int i = tid >> 3, b = tid & 7;
        s.xt[(64 + i)*8 + b] = s.in[b][81 + i];
    }
    __syncthreads();  // S6

    // ---------------- Phase I: mhid -> hbuf (NI=96 exact, no tail) -----------------------
    mlp_l1(s, tid, g_w1q_m, nullptr, msg_b1);
    __syncthreads();  // S7

    // ---------------- Phase J: msg + readout atomics ---------------------------------------
    {
        int b, d;
        float acc = mlp_l2(s, tid, g_w2t_m, msg_b2, b, d);
        s.msgv[b][d] = acc;
        dout[OFF_MSG + (((b*NCg + nc)*Cg + c)*Dg + d)] = acc;
        if (c >= Cg - ALPHAg)
            atomicAdd(&dout[OFF_READOUT + (b*NCg + nc)*Dg + d], acc * (1.f/ALPHAg));
    }
    __syncthreads();  // S8

    // ---------------- Phase K: Hebbian (multi-value butterfly) -----------------------------
    {
        const int kb = tid >> 5, kd = tid & 31;
        float msgval = s.msgv[kb][kd];
        {
            float v[16];
            #pragma unroll
            for (int k = 0; k < Kg; ++k)
                v[k] = msgval * prevmsg[((kb*NCg + nc)*Cg + s.conn[k])*Dg + kd];
            int k;
            float dot = multi_dot16(v, kd, k);
            if ((kd & 1) == 0) {
                float out = 0.9f * s.in[kb][k] + 0.003125f * dot;
                dout[OFF_HEB + (((kb*NCg + nc)*Cg + c)*Kg + k)] = out;
            }
        }
        if (bord) {
            float v[16];
            #pragma unroll
            for (int k = 0; k < KBg; ++k) {
                int j = s.bconn[k];
                v[k] = msgval * prevmsg[((kb*NCg + (j >> 4))*Cg + ALPHAg + (j & 15))*Dg + kd];
            }
            int k;
            float dot = multi_dot16(v, kd, k);
            if ((kd & 1) == 0) {
                float out = 0.9f * heb_trb[((kb*NCg + nc)*Bg + (c - ALPHAg))*KBg + k]
                          + 0.003125f * dot;
                dout[OFF_HEBB + (((kb*NCg + nc)*Bg + (c - ALPHAg))*KBg + k)] = out;
            }
        }
    }
}

// prep: zero readout + pack layer-1 weights (QL=24 quarters + state tail) + transpose w2
__global__ void prep_kernel(const float* __restrict__ sw1, const float* __restrict__ mw1,
                            const float* __restrict__ sw2, const float* __restrict__ mw2,
                            float* __restrict__ dout)
{
    int idx = blockIdx.x * 256 + threadIdx.x;
    if (idx < BSg*NCg*Dg) dout[OFF_READOUT + idx] = 0.f;
    if (idx < W1Q_SZ) {
        int r = idx & 3, t = idx >> 2;
        int ss = t & 63; t >>= 6;
        int p = t & 1; t >>= 1;
        int gl = t % 6, q = t / 6;
        int i = q*QL + gl*4 + r;          // 0..95 always
        int h = 2*ss + p;
        g_w1q_s[idx] = sw1[h*97 + i];
        g_w1q_m[idx] = mw1[h*96 + i];
    }
    if (idx < HSg) g_wtail_s[idx] = sw1[idx*97 + 96];
    if (idx < W2T_SZ) {
        int r = idx & 3, d = (idx >> 2) & 31, j = idx >> 7;
        g_w2t_s[idx] = sw2[d*HSg + 4*j + r];
        g_w2t_m[idx] = mw2[d*HMg + 4*j + r];
    }
}

extern "C" void kernel_launch(void* const* d_in, const int* in_sizes, int n_in,
                              void* d_out, int out_size)
{
    (void)in_sizes; (void)n_in; (void)out_size;
    const float* x           = (const float*)d_in[0];
    const float* h_in        = (const float*)d_in[1];
    const float* prevmsg     = (const float*)d_in[2];
    const float* decay_logit = (const float*)d_in[3];
    const float* prim        = (const float*)d_in[4];
    const float* heb_tr      = (const float*)d_in[5];
    const float* heb_trb     = (const float*)d_in[6];
    const float* state_w1    = (const float*)d_in[7];
    const float* state_b1    = (const float*)d_in[8];
    const float* state_w2    = (const float*)d_in[9];
    const float* state_b2    = (const float*)d_in[10];
    const float* msg_w1      = (const float*)d_in[11];
    const float* msg_b1      = (const float*)d_in[12];
    const float* msg_w2      = (const float*)d_in[13];
    const float* msg_b2      = (const float*)d_in[14];
    const float* mod_w1      = (const float*)d_in[15];
    const float* mod_b1      = (const float*)d_in[16];
    const float* mod_w2      = (const float*)d_in[17];
    const float* mod_b2      = (const float*)d_in[18];
    const float* neuron_id   = (const float*)d_in[19];
    const int*   conn_idx    = (const int*)d_in[20];
    const int*   bconn_idx   = (const int*)d_in[21];
    float* dout = (float*)d_out;

    cudaFuncSetAttribute(cell_kernel,
                         cudaFuncAttributeMaxDynamicSharedMemorySize,
                         (int)sizeof(Smem));

    prep_kernel<<<(BSg*NCg*Dg + 255)/256, 256>>>(state_w1, msg_w1, state_w2, msg_w2, dout);
    cell_kernel<<<NTOT, 256, sizeof(Smem)>>>(
        x, h_in, prevmsg, decay_logit, prim, heb_tr, heb_trb,
        state_b1, state_b2, msg_b1, msg_b2,
        mod_w1, mod_b1, mod_w2, mod_b2,
        neuron_id, conn_idx, bconn_idx, dout);
}